// round 15
// baseline (speedup 1.0000x reference)
#include <cuda_runtime.h>

#define NSAMP 16384
#define PTS   20
#define DIM   128
#define KNN   5
#define NANCH (NSAMP * PTS)
#define EDGES (NANCH * KNN)

#define SPB 3
#define NTH 64                         // 2 warps; 60 active workers
#define RSTRIDE 132                    // words/row: 16 chunks of [h0(16B)|h1(16B)] + pad
#define SAMP_STRIDE (PTS * RSTRIDE + 4)   // 2644 words
#define SMX_FLOATS (SPB * SAMP_STRIDE)    // 7932 words = 31.7 KB
#define PDQ 40                            // pd words per q: [ab(2)][h(2)][pa(10)]
#define PD_PER_S (PTS * PDQ)              // 800 words
#define SMPD_FLOATS (SPB * PD_PER_S)      // 2400 words = 9.6 KB

__device__ __forceinline__ void fma2(unsigned long long &acc,
                                     unsigned long long a,
                                     unsigned long long b) {
    asm("fma.rn.f32x2 %0, %1, %2, %0;" : "+l"(acc) : "l"(a), "l"(b));
}

// (a0+a1) + (a2+a3) over a 64-dim half: verified-safe order (R7/R10/R12/R13/R14)
__device__ __forceinline__ float chainsum(unsigned long long acc01,
                                          unsigned long long acc23) {
    float2 lo = *reinterpret_cast<float2*>(&acc01);
    float2 hi = *reinterpret_cast<float2*>(&acc23);
    return (lo.x + lo.y) + (hi.x + hi.y);
}

__device__ __forceinline__ int slot_of(int p) {   // h=0 slot; h=1 is +10
    return (p < 10) ? p : (10 + p);
}

__global__ void __launch_bounds__(NTH, 5)
knn_kernel(const float* __restrict__ x, float* __restrict__ out, int cap) {
    __shared__ __align__(16) float smx[SMX_FLOATS];
    __shared__ __align__(16) float smpd[SMPD_FLOATS];
    __shared__ float smnorm[SPB * PTS];

    const int tid = threadIdx.x;
    const int bs0 = blockIdx.x * SPB;

    // ---- Stage 3 samples gmem -> smem, half-interleaved chunk layout ----
    {
        const float4* xin = reinterpret_cast<const float4*>(x)
                          + (size_t)bs0 * (PTS * DIM / 4);
        #pragma unroll
        for (int t = tid; t < SPB * PTS * (DIM / 4); t += NTH) {
            int rc  = t >> 5;                   // row 0..59
            int f   = t & 31;                   // float4 idx in source row
            int s   = rc / PTS;
            int row = rc - s * PTS;
            int h   = f >> 4;
            int e   = f & 15;
            if (bs0 + s < NSAMP) {
                float4 v = xin[(size_t)rc * 32 + f];
                *reinterpret_cast<float4*>(
                    &smx[s * SAMP_STRIDE + row * RSTRIDE + e * 8 + h * 4]) = v;
            }
        }
    }
    __syncthreads();

    const bool act = (tid < SPB * PTS);           // 60 workers
    const int s  = act ? (tid / PTS) : 0;
    const int r  = act ? (tid - s * PTS) : 0;
    const bool valid = act && (bs0 + s < NSAMP);

    // ---- Phase 2: worker (s, h, pa) -> anchors pa & pa+10 on half h ----
    {
        const int h  = r / 10;
        const int pa = r - h * 10;
        const int pb = pa + 10;
        if (valid) {
            const float* base = &smx[s * SAMP_STRIDE + h * 4];
            unsigned long long xa[32], xb[32];    // 128 regs: both anchor rows
            {
                const ulonglong2* ra =
                    reinterpret_cast<const ulonglong2*>(base + pa * RSTRIDE);
                const ulonglong2* rb =
                    reinterpret_cast<const ulonglong2*>(base + pb * RSTRIDE);
                #pragma unroll
                for (int e = 0; e < 16; e++) {
                    ulonglong2 va = ra[2 * e];
                    ulonglong2 vb = rb[2 * e];
                    xa[2*e] = va.x; xa[2*e+1] = va.y;
                    xb[2*e] = vb.x; xb[2*e+1] = vb.y;
                }
            }
            float* pds = &smpd[s * PD_PER_S];
            const int sa = h * 10 + pa;           // ab=0 slot
            const int sb = 20 + h * 10 + pa;      // ab=1 slot
            // Full-row load burst + unroll-2: ptxas can overlap q+1 loads
            // with q's FMA block. Accumulation order identical to R14.
            #pragma unroll 2
            for (int q = 0; q < PTS; q++) {
                const ulonglong2* xq =
                    reinterpret_cast<const ulonglong2*>(base + q * RSTRIDE);
                ulonglong2 v[16];
                #pragma unroll
                for (int e = 0; e < 16; e++) v[e] = xq[2 * e];
                unsigned long long a01 = 0ull, a23 = 0ull;
                unsigned long long b01 = 0ull, b23 = 0ull;
                #pragma unroll
                for (int e = 0; e < 16; e++) {    // e ascending: frozen order
                    fma2(a01, xa[2*e],   v[e].x);
                    fma2(b01, xb[2*e],   v[e].x);
                    fma2(a23, xa[2*e+1], v[e].y);
                    fma2(b23, xb[2*e+1], v[e].y);
                }
                pds[q * PDQ + sa] = chainsum(a01, a23);
                pds[q * PDQ + sb] = chainsum(b01, b23);
            }
        }
    }
    __syncthreads();

    // ---- Phase 3a: norms from the diagonal (h0 + h1, verified order) ----
    const int p = r;
    if (valid) {
        const float* pds = &smpd[s * PD_PER_S];
        const int ob = slot_of(p);
        smnorm[s * PTS + p] = pds[p * PDQ + ob] + pds[p * PDQ + ob + 10];
    }
    __syncthreads();

    // ---- Phase 3b: assemble dots; exact (d2, q)-lex top-5; emit ----
    if (valid) {
        const float* pds = &smpd[s * PD_PER_S];
        const int ob = slot_of(p);
        const float sqp = smnorm[s * PTS + p];

        float kd[KNN];
        int   ki[KNN];
        #pragma unroll
        for (int m = 0; m < KNN; m++) { kd[m] = __int_as_float(0x7F800000); ki[m] = 0; }

        #pragma unroll
        for (int q = 0; q < PTS; q++) {
            const float dot = pds[q * PDQ + ob] + pds[q * PDQ + ob + 10]; // h0+h1
            const float sqq = smnorm[s * PTS + q];
            float dd = fmaxf(sqp + sqq - 2.0f * dot, 0.0f);   // ref clamp
            if (q == p) dd = __int_as_float(0x7F800000);      // exclude self
            float ck = dd; int ci = q;
            #pragma unroll
            for (int m = 0; m < KNN; m++) {       // stable insertion (strict <)
                bool sw = ck < kd[m];
                float tk = kd[m]; int ti = ki[m];
                kd[m] = sw ? ck : tk;  ki[m] = sw ? ci : ti;
                ck    = sw ? tk : ck;  ci    = sw ? ti : ci;
            }
        }

        const int w  = (bs0 + s) * PTS + p;
        const int obw = w * KNN;
        const float pf = (float)p;
        #pragma unroll
        for (int rr = 0; rr < KNN; rr++) {
            int iu = obw + rr;
            int iv = EDGES + obw + rr;
            if (iu < cap) out[iu] = pf;
            if (iv < cap) out[iv] = (float)ki[rr];
        }
    }
}

extern "C" void kernel_launch(void* const* d_in, const int* in_sizes, int n_in,
                              void* d_out, int out_size) {
    const float* x = (const float*)d_in[0];
    float* out = (float*)d_out;

    int cap = 2 * EDGES;
    if (out_size > 0 && out_size < 2 * EDGES) cap = out_size;

    const int grid = (NSAMP + SPB - 1) / SPB;   // 5462
    knn_kernel<<<grid, NTH>>>(x, out, cap);
}